// round 5
// baseline (speedup 1.0000x reference)
#include <cuda_runtime.h>

// EMA y_t = (1-w)*y_{t-1} + w*x_t — decoupled-lookback scan, v4.
// v3 scheduling (batch-fast grid) + occupancy fix: the 32-elem register stash
// is gone; Phase C re-reads x through L2 (Phase A primes it with __ldcg).
// Regs drop 64 -> ~30, launch_bounds (256,8) -> 100% theoretical occupancy,
// doubling memory parallelism. Loads grouped 8-wide to bound live registers.

#define TT   8192
#define CC   256
#define LL   32
#define NCH  (TT / LL)   // 256 chunks per batch row
#define MAXB 16

// packed carry: high 32 = flag (0 empty / 1 aggregate / 2 inclusive prefix),
// low 32 = float payload. Zeroed each launch.
__device__ unsigned long long g_carry[MAXB * NCH * CC];

__global__ void ema_clear_kernel() {
    int i = blockIdx.x * blockDim.x + threadIdx.x;
    ((ulonglong2*)g_carry)[i] = make_ulonglong2(0ULL, 0ULL);
}

__global__ __launch_bounds__(CC, 8) void ema_scan_kernel(
    const float* __restrict__ x,
    const float* __restrict__ y0,
    const float* __restrict__ smooth,
    float* __restrict__ out,
    int B)
{
    // batch-fast: predecessor (k-1,b) is exactly B bids lower, so a wave of
    // ~1184 CTAs spans only ~74 chunk-levels -> short lookback chains.
    const int b = blockIdx.x % B;
    const int k = blockIdx.x / B;
    const int c = threadIdx.x;

    const float w = fminf(fmaxf(smooth[c], 0.0f), 1.0f);
    const float a = 1.0f - w;

    // ---- Phase A: stream chunk (prime L2), compute zero-start aggregate ----
    const float* xp = x + ((size_t)(b * TT + k * LL) * CC + c);
    float e = 0.0f;
#pragma unroll
    for (int g8 = 0; g8 < LL / 8; g8++) {
        float v[8];
#pragma unroll
        for (int i = 0; i < 8; i++) v[i] = __ldcg(xp + (g8 * 8 + i) * CC);
#pragma unroll
        for (int i = 0; i < 8; i++) e = fmaf(a, e, w * v[i]);
    }

    // A_L = a^32 via 5 squarings
    float A2 = a * a;
    float A4 = A2 * A2;
    float A8 = A4 * A4;
    float A16 = A8 * A8;
    const float AL = A16 * A16;

    volatile unsigned long long* cb = g_carry + (size_t)(b * NCH) * CC;

    // publish aggregate (flag=1): aligned 8B store = atomic, no fence needed
    cb[(size_t)k * CC + c] =
        (1ULL << 32) | (unsigned long long)__float_as_uint(e);

    // ---- Lookback: fold predecessor aggregates, short-circuit on prefixes ----
    float acc;
    if (k == 0) {
        acc = y0[b * CC + c];
    } else {
        acc = 0.0f;
        float m = 1.0f;
        int j = k - 1;
        bool done = false;
        while (!done) {
            const int g = (j + 1 < 8) ? (j + 1) : 8;
            unsigned long long v[8];
            bool allset;
            do {  // batched spin: 8 independent volatile 8B reads per round
                allset = true;
#pragma unroll
                for (int u = 0; u < 8; u++) {
                    if (u < g) {
                        v[u] = cb[(size_t)(j - u) * CC + c];
                        if ((unsigned)(v[u] >> 32) == 0u) allset = false;
                    }
                }
            } while (!allset);
#pragma unroll
            for (int u = 0; u < 8; u++) {
                if (u < g) {
                    const unsigned f = (unsigned)(v[u] >> 32);
                    const float val = __uint_as_float((unsigned)(v[u] & 0xFFFFFFFFu));
                    acc = fmaf(m, val, acc);
                    if (f == 2u) { done = true; break; }  // inclusive prefix
                    m *= AL;                              // zero-start aggregate
                }
            }
            if (!done) {
                j -= g;
                if (j < 0) {  // all aggregates folded; add initial-state term
                    acc = fmaf(m, y0[b * CC + c], acc);
                    done = true;
                }
            }
        }
    }

    // publish inclusive prefix (flag=2) so downstream chunks short-circuit
    const float P = fmaf(AL, acc, e);
    cb[(size_t)k * CC + c] =
        (2ULL << 32) | (unsigned long long)__float_as_uint(P);

    // ---- Phase C: replay recurrence (x re-read hits L2), stream outputs ----
    float y = acc;
    float* op = out + ((size_t)(b * TT + k * LL) * CC + c);
#pragma unroll
    for (int g8 = 0; g8 < LL / 8; g8++) {
        float v[8];
#pragma unroll
        for (int i = 0; i < 8; i++) v[i] = __ldcg(xp + (g8 * 8 + i) * CC);
#pragma unroll
        for (int i = 0; i < 8; i++) {
            y = fmaf(a, y, w * v[i]);
            __stcs(op + (g8 * 8 + i) * CC, y);
        }
    }
}

extern "C" void kernel_launch(void* const* d_in, const int* in_sizes, int n_in,
                              void* d_out, int out_size) {
    const float* x      = (const float*)d_in[0];  // [B, T, C]
    const float* y0     = (const float*)d_in[1];  // [B, C]
    const float* smooth = (const float*)d_in[2];  // [C]
    float* out          = (float*)d_out;

    const int B = in_sizes[0] / (TT * CC);

    ema_clear_kernel<<<(MAXB * NCH * CC / 2) / 256, 256>>>();
    ema_scan_kernel<<<B * NCH, CC>>>(x, y0, smooth, out, B);
}

// round 7
// speedup vs baseline: 1.4635x; 1.4635x over previous
#include <cuda_runtime.h>

// EMA y_t = (1-w)*y_{t-1} + w*x_t — decoupled-lookback scan, v5.
// Single-read register stash (traffic-minimal, per R4 post-mortem: L2 re-read
// costs +140MB DRAM) + occupancy fix: chunk halved to LL=16 so the stash is
// 16 regs and launch_bounds(256,6) reaches 75% theoretical occupancy.
// Stash holds the zero-entry partial scan ỹ_i; after lookback the final
// output is the dependency-free fixup out_i = ỹ_i + a^(i+1) * acc.

#define TT   8192
#define CC   256
#define LL   16
#define NCH  (TT / LL)   // 512 chunks per batch row
#define MAXB 16

// packed carry: high 32 = flag (0 empty / 1 aggregate / 2 inclusive prefix),
// low 32 = float payload. Zeroed each launch (readers spin on flag!=0).
__device__ unsigned long long g_carry[MAXB * NCH * CC];

__global__ void ema_clear_kernel(int n2) {
    int i = blockIdx.x * blockDim.x + threadIdx.x;
    if (i < n2) ((ulonglong2*)g_carry)[i] = make_ulonglong2(0ULL, 0ULL);
}

__global__ __launch_bounds__(CC, 6) void ema_scan_kernel(
    const float* __restrict__ x,
    const float* __restrict__ y0,
    const float* __restrict__ smooth,
    float* __restrict__ out,
    int B)
{
    // batch-fast: predecessor (k-1,b) is exactly B bids lower; a ~900-CTA
    // wave spans only ~55 chunk-levels -> short, mostly-resolved lookbacks.
    const int b = blockIdx.x % B;
    const int k = blockIdx.x / B;
    const int c = threadIdx.x;

    const float w = fminf(fmaxf(smooth[c], 0.0f), 1.0f);
    const float a = 1.0f - w;

    // ---- Phase A: single read of the chunk; stash the zero-entry partial
    //      scan ys[i] = sum_{j<=i} a^(i-j) * w * x_j  (serial, 4cyc FMA chain
    //      hidden under the loads). ----
    const float* xp = x + ((size_t)(b * TT + k * LL) * CC + c);
    float ys[LL];
    float e = 0.0f;
#pragma unroll
    for (int i = 0; i < LL; i++) {
        e = fmaf(a, e, w * __ldcs(xp + i * CC));
        ys[i] = e;
    }

    // A_L = a^16 via 4 squarings
    float A2 = a * a;
    float A4 = A2 * A2;
    float A8 = A4 * A4;
    const float AL = A8 * A8;

    volatile unsigned long long* cb = g_carry + (size_t)(b * NCH) * CC;

    // publish aggregate (flag=1): aligned 8B store = atomic, no fence needed
    cb[(size_t)k * CC + c] =
        (1ULL << 32) | (unsigned long long)__float_as_uint(e);

    // ---- Lookback: fold predecessor aggregates, short-circuit on prefixes ----
    float acc;
    if (k == 0) {
        acc = y0[b * CC + c];
    } else {
        acc = 0.0f;
        float m = 1.0f;
        int j = k - 1;
        bool done = false;
        while (!done) {
            const int g = (j + 1 < 4) ? (j + 1) : 4;
            unsigned long long v[4];
            bool allset;
            do {  // batched spin: 4 independent volatile 8B reads per round
                allset = true;
#pragma unroll
                for (int u = 0; u < 4; u++) {
                    if (u < g) {
                        v[u] = cb[(size_t)(j - u) * CC + c];
                        if ((unsigned)(v[u] >> 32) == 0u) allset = false;
                    }
                }
            } while (!allset);
#pragma unroll
            for (int u = 0; u < 4; u++) {
                if (u < g) {
                    const unsigned f = (unsigned)(v[u] >> 32);
                    const float val = __uint_as_float((unsigned)(v[u] & 0xFFFFFFFFu));
                    acc = fmaf(m, val, acc);
                    if (f == 2u) { done = true; break; }  // inclusive prefix
                    m *= AL;                              // zero-start aggregate
                }
            }
            if (!done) {
                j -= g;
                if (j < 0) {  // all aggregates folded; add initial-state term
                    acc = fmaf(m, y0[b * CC + c], acc);
                    done = true;
                }
            }
        }
    }

    // publish inclusive prefix (flag=2) so downstream chunks short-circuit
    const float P = fmaf(AL, acc, e);
    cb[(size_t)k * CC + c] =
        (2ULL << 32) | (unsigned long long)__float_as_uint(P);

    // ---- Phase C: dependency-free fixup from the stash, stream outputs ----
    float* op = out + ((size_t)(b * TT + k * LL) * CC + c);
    float pw = a;   // a^(i+1)
#pragma unroll
    for (int i = 0; i < LL; i++) {
        __stcs(op + i * CC, fmaf(pw, acc, ys[i]));
        pw *= a;
    }
}

extern "C" void kernel_launch(void* const* d_in, const int* in_sizes, int n_in,
                              void* d_out, int out_size) {
    const float* x      = (const float*)d_in[0];  // [B, T, C]
    const float* y0     = (const float*)d_in[1];  // [B, C]
    const float* smooth = (const float*)d_in[2];  // [C]
    float* out          = (float*)d_out;

    const int B = in_sizes[0] / (TT * CC);

    const int n2 = (B * NCH * CC) / 2;           // ulonglong2 words to clear
    ema_clear_kernel<<<(n2 + 255) / 256, 256>>>(n2);
    ema_scan_kernel<<<B * NCH, CC>>>(x, y0, smooth, out, B);
}